// round 10
// baseline (speedup 1.0000x reference)
#include <cuda_runtime.h>
#include <cstring>

#define K_DIM   64
#define TILE    128
#define XT_STR  132   // padded stride (multiple of 4 for aligned float4, breaks bank conflicts)

#define MAX_AGENTS 50000

// Scratch: per-agent pooled features (segment_sum output). Static device array
// (no cudaMalloc allowed anywhere).
__device__ float g_summ[MAX_AGENTS * K_DIM];

// Packed dual-FMA (Blackwell f32x2): two independent fp32 FMAs per instruction.
__device__ __forceinline__ float2 ffma2(float2 a, float2 b, float2 c) {
    unsigned long long au, bu, cu, du;
    memcpy(&au, &a, 8); memcpy(&bu, &b, 8); memcpy(&cu, &c, 8);
    asm("fma.rn.f32x2 %0, %1, %2, %3;" : "=l"(du) : "l"(au), "l"(bu), "l"(cu));
    float2 d; memcpy(&d, &du, 8); return d;
}

__global__ void zero_kernel(int n4) {
    int i = blockIdx.x * blockDim.x + threadIdx.x;
    if (i < n4) {
        reinterpret_cast<float4*>(g_summ)[i] = make_float4(0.f, 0.f, 0.f, 0.f);
    }
}

// ---------------------------------------------------------------------------
// phi kernel: h2 = relu(X @ W1 + b1) @ W2 + b2, then segment-sum into g_summ.
// Tile = 128 rows. 256 threads: thread = 8 rows x 4 cols microtile, rows packed
// into f32x2 pairs. Sorted segment_ids -> per-thread run compression before atomics.
// ---------------------------------------------------------------------------
extern __shared__ float smem_f[];

__global__ __launch_bounds__(256, 2)
void phi_kernel(const float* __restrict__ nb,
                const float* __restrict__ w1, const float* __restrict__ b1,
                const float* __restrict__ w2, const float* __restrict__ b2,
                const int*   __restrict__ seg,
                int nrows)
{
    float* w1s = smem_f;                    // 64*64 = 4096
    float* w2s = w1s + 4096;                // 4096
    float* xT  = w2s + 4096;                // 64*132 = 8448 (transposed: xT[k][row])
    float* hT  = xT  + 64 * XT_STR;         // 8448
    float* b1s = hT  + 64 * XT_STR;         // 64
    float* b2s = b1s + 64;                  // 64
    int*   segs = (int*)(b2s + 64);         // 128

    const int tid = threadIdx.x;

    // Stage weights + biases
    #pragma unroll 4
    for (int i = tid; i < 4096; i += 256) { w1s[i] = w1[i]; w2s[i] = w2[i]; }
    if (tid < 64) { b1s[tid] = b1[tid]; b2s[tid] = b2[tid]; }

    const int base = blockIdx.x * TILE;

    // Load X tile transposed (coalesced gmem float4 reads, strided smem writes)
    const float4* nb4 = reinterpret_cast<const float4*>(nb + (long long)base * K_DIM);
    #pragma unroll
    for (int i = tid; i < TILE * K_DIM / 4; i += 256) {
        int idx = i * 4;
        int r = idx >> 6;           // row in tile
        int c = idx & 63;           // first of 4 columns
        float4 v = (base + r < nrows) ? nb4[i] : make_float4(0.f, 0.f, 0.f, 0.f);
        xT[(c + 0) * XT_STR + r] = v.x;
        xT[(c + 1) * XT_STR + r] = v.y;
        xT[(c + 2) * XT_STR + r] = v.z;
        xT[(c + 3) * XT_STR + r] = v.w;
    }
    if (tid < TILE) segs[tid] = (base + tid < nrows) ? seg[base + tid] : -1;
    __syncthreads();

    const int tx = tid & 15;        // col group: 4 cols
    const int ty = tid >> 4;        // row group: 8 rows
    const int row0 = ty * 8;
    const int col0 = tx * 4;

    float2 acc[4][4];               // acc[p][c]: rows (row0+2p, row0+2p+1), col col0+c

    // ---- Layer 1 ----
    #pragma unroll
    for (int c = 0; c < 4; c++) {
        float bv = b1s[col0 + c];
        #pragma unroll
        for (int p = 0; p < 4; p++) acc[p][c] = make_float2(bv, bv);
    }
    #pragma unroll 4
    for (int k = 0; k < K_DIM; k++) {
        float4 a0 = *reinterpret_cast<const float4*>(&xT[k * XT_STR + row0]);
        float4 a1 = *reinterpret_cast<const float4*>(&xT[k * XT_STR + row0 + 4]);
        float4 wv = *reinterpret_cast<const float4*>(&w1s[k * K_DIM + col0]);
        float2 pr[4] = { make_float2(a0.x, a0.y), make_float2(a0.z, a0.w),
                         make_float2(a1.x, a1.y), make_float2(a1.z, a1.w) };
        float wa[4] = { wv.x, wv.y, wv.z, wv.w };
        #pragma unroll
        for (int c = 0; c < 4; c++) {
            float2 wb = make_float2(wa[c], wa[c]);
            #pragma unroll
            for (int p = 0; p < 4; p++) acc[p][c] = ffma2(pr[p], wb, acc[p][c]);
        }
    }
    // relu -> hT (transposed, float2 stores of row pairs)
    #pragma unroll
    for (int c = 0; c < 4; c++) {
        #pragma unroll
        for (int p = 0; p < 4; p++) {
            float2 v = acc[p][c];
            v.x = fmaxf(v.x, 0.f); v.y = fmaxf(v.y, 0.f);
            *reinterpret_cast<float2*>(&hT[(col0 + c) * XT_STR + row0 + 2 * p]) = v;
        }
    }
    __syncthreads();

    // ---- Layer 2 ----
    #pragma unroll
    for (int c = 0; c < 4; c++) {
        float bv = b2s[col0 + c];
        #pragma unroll
        for (int p = 0; p < 4; p++) acc[p][c] = make_float2(bv, bv);
    }
    #pragma unroll 4
    for (int k = 0; k < K_DIM; k++) {
        float4 a0 = *reinterpret_cast<const float4*>(&hT[k * XT_STR + row0]);
        float4 a1 = *reinterpret_cast<const float4*>(&hT[k * XT_STR + row0 + 4]);
        float4 wv = *reinterpret_cast<const float4*>(&w2s[k * K_DIM + col0]);
        float2 pr[4] = { make_float2(a0.x, a0.y), make_float2(a0.z, a0.w),
                         make_float2(a1.x, a1.y), make_float2(a1.z, a1.w) };
        float wa[4] = { wv.x, wv.y, wv.z, wv.w };
        #pragma unroll
        for (int c = 0; c < 4; c++) {
            float2 wb = make_float2(wa[c], wa[c]);
            #pragma unroll
            for (int p = 0; p < 4; p++) acc[p][c] = ffma2(pr[p], wb, acc[p][c]);
        }
    }

    // ---- Segment reduction epilogue ----
    // segment_ids sorted -> each thread's 8 contiguous rows form few runs.
    const int grow = base + row0;
    int cur = -1;
    float s0 = 0.f, s1 = 0.f, s2 = 0.f, s3 = 0.f;
    #pragma unroll
    for (int i = 0; i < 8; i++) {
        if (grow + i >= nrows) break;
        int sid = segs[row0 + i];
        int p = i >> 1;
        float v0, v1, v2, v3;
        if (i & 1) { v0 = acc[p][0].y; v1 = acc[p][1].y; v2 = acc[p][2].y; v3 = acc[p][3].y; }
        else       { v0 = acc[p][0].x; v1 = acc[p][1].x; v2 = acc[p][2].x; v3 = acc[p][3].x; }
        if (sid == cur) { s0 += v0; s1 += v1; s2 += v2; s3 += v3; }
        else {
            if (cur >= 0) {
                float* dst = &g_summ[cur * K_DIM + col0];
                atomicAdd(dst + 0, s0); atomicAdd(dst + 1, s1);
                atomicAdd(dst + 2, s2); atomicAdd(dst + 3, s3);
            }
            cur = sid; s0 = v0; s1 = v1; s2 = v2; s3 = v3;
        }
    }
    if (cur >= 0) {
        float* dst = &g_summ[cur * K_DIM + col0];
        atomicAdd(dst + 0, s0); atomicAdd(dst + 1, s1);
        atomicAdd(dst + 2, s2); atomicAdd(dst + 3, s3);
    }
}

// ---------------------------------------------------------------------------
// rho kernel: out = relu(summ @ rho_w1 + rho_b1) @ rho_w2 + rho_b2
// ---------------------------------------------------------------------------
__global__ __launch_bounds__(256, 2)
void rho_kernel(const float* __restrict__ w1, const float* __restrict__ b1,
                const float* __restrict__ w2, const float* __restrict__ b2,
                float* __restrict__ out, int nAgents)
{
    float* w1s = smem_f;                    // 4096
    float* xT  = w1s + 4096;                // 8448
    float* hT  = xT  + 64 * XT_STR;         // 8448
    float* b1s = hT  + 64 * XT_STR;         // 64
    float* w2b = b1s + 64;                  // 128 (64x2)
    float* b2b = w2b + 128;                 // 2

    const int tid = threadIdx.x;

    #pragma unroll 4
    for (int i = tid; i < 4096; i += 256) w1s[i] = w1[i];
    if (tid < 64)  b1s[tid] = b1[tid];
    if (tid < 128) w2b[tid] = w2[tid];
    if (tid < 2)   b2b[tid] = b2[tid];

    const int base = blockIdx.x * TILE;

    const float4* x4 = reinterpret_cast<const float4*>(g_summ + (long long)base * K_DIM);
    #pragma unroll
    for (int i = tid; i < TILE * K_DIM / 4; i += 256) {
        int idx = i * 4;
        int r = idx >> 6;
        int c = idx & 63;
        float4 v = (base + r < nAgents) ? x4[i] : make_float4(0.f, 0.f, 0.f, 0.f);
        xT[(c + 0) * XT_STR + r] = v.x;
        xT[(c + 1) * XT_STR + r] = v.y;
        xT[(c + 2) * XT_STR + r] = v.z;
        xT[(c + 3) * XT_STR + r] = v.w;
    }
    __syncthreads();

    const int tx = tid & 15;
    const int ty = tid >> 4;
    const int row0 = ty * 8;
    const int col0 = tx * 4;

    float2 acc[4][4];
    #pragma unroll
    for (int c = 0; c < 4; c++) {
        float bv = b1s[col0 + c];
        #pragma unroll
        for (int p = 0; p < 4; p++) acc[p][c] = make_float2(bv, bv);
    }
    #pragma unroll 4
    for (int k = 0; k < K_DIM; k++) {
        float4 a0 = *reinterpret_cast<const float4*>(&xT[k * XT_STR + row0]);
        float4 a1 = *reinterpret_cast<const float4*>(&xT[k * XT_STR + row0 + 4]);
        float4 wv = *reinterpret_cast<const float4*>(&w1s[k * K_DIM + col0]);
        float2 pr[4] = { make_float2(a0.x, a0.y), make_float2(a0.z, a0.w),
                         make_float2(a1.x, a1.y), make_float2(a1.z, a1.w) };
        float wa[4] = { wv.x, wv.y, wv.z, wv.w };
        #pragma unroll
        for (int c = 0; c < 4; c++) {
            float2 wb = make_float2(wa[c], wa[c]);
            #pragma unroll
            for (int p = 0; p < 4; p++) acc[p][c] = ffma2(pr[p], wb, acc[p][c]);
        }
    }
    // relu -> hT
    #pragma unroll
    for (int c = 0; c < 4; c++) {
        #pragma unroll
        for (int p = 0; p < 4; p++) {
            float2 v = acc[p][c];
            v.x = fmaxf(v.x, 0.f); v.y = fmaxf(v.y, 0.f);
            *reinterpret_cast<float2*>(&hT[(col0 + c) * XT_STR + row0 + 2 * p]) = v;
        }
    }
    __syncthreads();

    // Layer 2: 64 -> 2. One output element per thread (128 rows x 2 cols = 256).
    int r = tid >> 1;
    int c = tid & 1;
    if (base + r < nAgents) {
        float s = b2b[c];
        #pragma unroll 8
        for (int k = 0; k < K_DIM; k++) {
            s = fmaf(hT[k * XT_STR + r], w2b[k * 2 + c], s);
        }
        out[(base + r) * 2 + c] = s;
    }
}

// ---------------------------------------------------------------------------
extern "C" void kernel_launch(void* const* d_in, const int* in_sizes, int n_in,
                              void* d_out, int out_size)
{
    const float* neighbors = (const float*)d_in[0];
    const float* phi_w1    = (const float*)d_in[1];
    const float* phi_b1    = (const float*)d_in[2];
    const float* phi_w2    = (const float*)d_in[3];
    const float* phi_b2    = (const float*)d_in[4];
    const float* rho_w1    = (const float*)d_in[5];
    const float* rho_b1    = (const float*)d_in[6];
    const float* rho_w2    = (const float*)d_in[7];
    const float* rho_b2    = (const float*)d_in[8];
    const int*   seg       = (const int*)d_in[9];
    float* out = (float*)d_out;

    const int nN = in_sizes[9];        // N_NEIGHBORS (count of segment_ids)
    const int nA = out_size / 2;       // N_AGENTS

    const int PHI_SMEM = (4096 + 4096 + 64 * XT_STR + 64 * XT_STR + 64 + 64) * 4 + TILE * 4; // 101376
    const int RHO_SMEM = (4096 + 64 * XT_STR + 64 * XT_STR + 64 + 128 + 2) * 4;              // 84744

    cudaFuncSetAttribute(phi_kernel, cudaFuncAttributeMaxDynamicSharedMemorySize, PHI_SMEM);
    cudaFuncSetAttribute(rho_kernel, cudaFuncAttributeMaxDynamicSharedMemorySize, RHO_SMEM);

    // 1) zero the segment-sum scratch (full static buffer)
    const int n4 = MAX_AGENTS * K_DIM / 4;
    zero_kernel<<<(n4 + 255) / 256, 256>>>(n4);

    // 2) phi MLP + segment sum
    const int phi_blocks = (nN + TILE - 1) / TILE;
    phi_kernel<<<phi_blocks, 256, PHI_SMEM>>>(neighbors, phi_w1, phi_b1, phi_w2, phi_b2, seg, nN);

    // 3) rho MLP
    const int rho_blocks = (nA + TILE - 1) / TILE;
    rho_kernel<<<rho_blocks, 256, RHO_SMEM>>>(rho_w1, rho_b1, rho_w2, rho_b2, out, nA);
}

// round 11
// speedup vs baseline: 1.0036x; 1.0036x over previous
#include <cuda_runtime.h>
#include <cstring>

#define K_DIM   64
#define TILE    128
#define XT_STR  132   // padded stride (multiple of 4 for aligned float4, breaks bank conflicts)

#define MAX_AGENTS 50000

// Scratch: per-agent pooled features (segment_sum output). Static device array
// (no cudaMalloc allowed anywhere).
__device__ float g_summ[MAX_AGENTS * K_DIM];

// Packed dual-FMA (Blackwell f32x2): two independent fp32 FMAs per instruction.
__device__ __forceinline__ float2 ffma2(float2 a, float2 b, float2 c) {
    unsigned long long au, bu, cu, du;
    memcpy(&au, &a, 8); memcpy(&bu, &b, 8); memcpy(&cu, &c, 8);
    asm("fma.rn.f32x2 %0, %1, %2, %3;" : "=l"(du) : "l"(au), "l"(bu), "l"(cu));
    float2 d; memcpy(&d, &du, 8); return d;
}

__global__ void zero_kernel(int n4) {
    int i = blockIdx.x * blockDim.x + threadIdx.x;
    if (i < n4) {
        reinterpret_cast<float4*>(g_summ)[i] = make_float4(0.f, 0.f, 0.f, 0.f);
    }
}

// ---------------------------------------------------------------------------
// phi kernel: h2 = relu(X @ W1 + b1) @ W2 + b2, then segment-sum into g_summ.
// Tile = 128 rows. 256 threads: thread = 8 rows x 4 cols microtile, rows packed
// into f32x2 pairs. Sorted segment_ids -> per-thread run compression before atomics.
// ---------------------------------------------------------------------------
extern __shared__ float smem_f[];

__global__ __launch_bounds__(256, 2)
void phi_kernel(const float* __restrict__ nb,
                const float* __restrict__ w1, const float* __restrict__ b1,
                const float* __restrict__ w2, const float* __restrict__ b2,
                const int*   __restrict__ seg,
                int nrows)
{
    float* w1s = smem_f;                    // 64*64 = 4096
    float* w2s = w1s + 4096;                // 4096
    float* xT  = w2s + 4096;                // 64*132 = 8448 (transposed: xT[k][row])
    float* hT  = xT  + 64 * XT_STR;         // 8448
    float* b1s = hT  + 64 * XT_STR;         // 64
    float* b2s = b1s + 64;                  // 64
    int*   segs = (int*)(b2s + 64);         // 128

    const int tid = threadIdx.x;

    // Stage weights + biases
    #pragma unroll 4
    for (int i = tid; i < 4096; i += 256) { w1s[i] = w1[i]; w2s[i] = w2[i]; }
    if (tid < 64) { b1s[tid] = b1[tid]; b2s[tid] = b2[tid]; }

    const int base = blockIdx.x * TILE;

    // Load X tile transposed (coalesced gmem float4 reads, strided smem writes)
    const float4* nb4 = reinterpret_cast<const float4*>(nb + (long long)base * K_DIM);
    #pragma unroll
    for (int i = tid; i < TILE * K_DIM / 4; i += 256) {
        int idx = i * 4;
        int r = idx >> 6;           // row in tile
        int c = idx & 63;           // first of 4 columns
        float4 v = (base + r < nrows) ? nb4[i] : make_float4(0.f, 0.f, 0.f, 0.f);
        xT[(c + 0) * XT_STR + r] = v.x;
        xT[(c + 1) * XT_STR + r] = v.y;
        xT[(c + 2) * XT_STR + r] = v.z;
        xT[(c + 3) * XT_STR + r] = v.w;
    }
    if (tid < TILE) segs[tid] = (base + tid < nrows) ? seg[base + tid] : -1;
    __syncthreads();

    const int tx = tid & 15;        // col group: 4 cols
    const int ty = tid >> 4;        // row group: 8 rows
    const int row0 = ty * 8;
    const int col0 = tx * 4;

    float2 acc[4][4];               // acc[p][c]: rows (row0+2p, row0+2p+1), col col0+c

    // ---- Layer 1 ----
    #pragma unroll
    for (int c = 0; c < 4; c++) {
        float bv = b1s[col0 + c];
        #pragma unroll
        for (int p = 0; p < 4; p++) acc[p][c] = make_float2(bv, bv);
    }
    #pragma unroll 4
    for (int k = 0; k < K_DIM; k++) {
        float4 a0 = *reinterpret_cast<const float4*>(&xT[k * XT_STR + row0]);
        float4 a1 = *reinterpret_cast<const float4*>(&xT[k * XT_STR + row0 + 4]);
        float4 wv = *reinterpret_cast<const float4*>(&w1s[k * K_DIM + col0]);
        float2 pr[4] = { make_float2(a0.x, a0.y), make_float2(a0.z, a0.w),
                         make_float2(a1.x, a1.y), make_float2(a1.z, a1.w) };
        float wa[4] = { wv.x, wv.y, wv.z, wv.w };
        #pragma unroll
        for (int c = 0; c < 4; c++) {
            float2 wb = make_float2(wa[c], wa[c]);
            #pragma unroll
            for (int p = 0; p < 4; p++) acc[p][c] = ffma2(pr[p], wb, acc[p][c]);
        }
    }
    // relu -> hT (transposed, float2 stores of row pairs)
    #pragma unroll
    for (int c = 0; c < 4; c++) {
        #pragma unroll
        for (int p = 0; p < 4; p++) {
            float2 v = acc[p][c];
            v.x = fmaxf(v.x, 0.f); v.y = fmaxf(v.y, 0.f);
            *reinterpret_cast<float2*>(&hT[(col0 + c) * XT_STR + row0 + 2 * p]) = v;
        }
    }
    __syncthreads();

    // ---- Layer 2 ----
    #pragma unroll
    for (int c = 0; c < 4; c++) {
        float bv = b2s[col0 + c];
        #pragma unroll
        for (int p = 0; p < 4; p++) acc[p][c] = make_float2(bv, bv);
    }
    #pragma unroll 4
    for (int k = 0; k < K_DIM; k++) {
        float4 a0 = *reinterpret_cast<const float4*>(&hT[k * XT_STR + row0]);
        float4 a1 = *reinterpret_cast<const float4*>(&hT[k * XT_STR + row0 + 4]);
        float4 wv = *reinterpret_cast<const float4*>(&w2s[k * K_DIM + col0]);
        float2 pr[4] = { make_float2(a0.x, a0.y), make_float2(a0.z, a0.w),
                         make_float2(a1.x, a1.y), make_float2(a1.z, a1.w) };
        float wa[4] = { wv.x, wv.y, wv.z, wv.w };
        #pragma unroll
        for (int c = 0; c < 4; c++) {
            float2 wb = make_float2(wa[c], wa[c]);
            #pragma unroll
            for (int p = 0; p < 4; p++) acc[p][c] = ffma2(pr[p], wb, acc[p][c]);
        }
    }

    // ---- Segment reduction epilogue ----
    // segment_ids sorted -> each thread's 8 contiguous rows form few runs.
    const int grow = base + row0;
    int cur = -1;
    float s0 = 0.f, s1 = 0.f, s2 = 0.f, s3 = 0.f;
    #pragma unroll
    for (int i = 0; i < 8; i++) {
        if (grow + i >= nrows) break;
        int sid = segs[row0 + i];
        int p = i >> 1;
        float v0, v1, v2, v3;
        if (i & 1) { v0 = acc[p][0].y; v1 = acc[p][1].y; v2 = acc[p][2].y; v3 = acc[p][3].y; }
        else       { v0 = acc[p][0].x; v1 = acc[p][1].x; v2 = acc[p][2].x; v3 = acc[p][3].x; }
        if (sid == cur) { s0 += v0; s1 += v1; s2 += v2; s3 += v3; }
        else {
            if (cur >= 0) {
                float* dst = &g_summ[cur * K_DIM + col0];
                atomicAdd(dst + 0, s0); atomicAdd(dst + 1, s1);
                atomicAdd(dst + 2, s2); atomicAdd(dst + 3, s3);
            }
            cur = sid; s0 = v0; s1 = v1; s2 = v2; s3 = v3;
        }
    }
    if (cur >= 0) {
        float* dst = &g_summ[cur * K_DIM + col0];
        atomicAdd(dst + 0, s0); atomicAdd(dst + 1, s1);
        atomicAdd(dst + 2, s2); atomicAdd(dst + 3, s3);
    }
}

// ---------------------------------------------------------------------------
// rho kernel: out = relu(summ @ rho_w1 + rho_b1) @ rho_w2 + rho_b2
// ---------------------------------------------------------------------------
__global__ __launch_bounds__(256, 2)
void rho_kernel(const float* __restrict__ w1, const float* __restrict__ b1,
                const float* __restrict__ w2, const float* __restrict__ b2,
                float* __restrict__ out, int nAgents)
{
    float* w1s = smem_f;                    // 4096
    float* xT  = w1s + 4096;                // 8448
    float* hT  = xT  + 64 * XT_STR;         // 8448
    float* b1s = hT  + 64 * XT_STR;         // 64
    float* w2b = b1s + 64;                  // 128 (64x2)
    float* b2b = w2b + 128;                 // 2

    const int tid = threadIdx.x;

    #pragma unroll 4
    for (int i = tid; i < 4096; i += 256) w1s[i] = w1[i];
    if (tid < 64)  b1s[tid] = b1[tid];
    if (tid < 128) w2b[tid] = w2[tid];
    if (tid < 2)   b2b[tid] = b2[tid];

    const int base = blockIdx.x * TILE;

    const float4* x4 = reinterpret_cast<const float4*>(g_summ + (long long)base * K_DIM);
    #pragma unroll
    for (int i = tid; i < TILE * K_DIM / 4; i += 256) {
        int idx = i * 4;
        int r = idx >> 6;
        int c = idx & 63;
        float4 v = (base + r < nAgents) ? x4[i] : make_float4(0.f, 0.f, 0.f, 0.f);
        xT[(c + 0) * XT_STR + r] = v.x;
        xT[(c + 1) * XT_STR + r] = v.y;
        xT[(c + 2) * XT_STR + r] = v.z;
        xT[(c + 3) * XT_STR + r] = v.w;
    }
    __syncthreads();

    const int tx = tid & 15;
    const int ty = tid >> 4;
    const int row0 = ty * 8;
    const int col0 = tx * 4;

    float2 acc[4][4];
    #pragma unroll
    for (int c = 0; c < 4; c++) {
        float bv = b1s[col0 + c];
        #pragma unroll
        for (int p = 0; p < 4; p++) acc[p][c] = make_float2(bv, bv);
    }
    #pragma unroll 4
    for (int k = 0; k < K_DIM; k++) {
        float4 a0 = *reinterpret_cast<const float4*>(&xT[k * XT_STR + row0]);
        float4 a1 = *reinterpret_cast<const float4*>(&xT[k * XT_STR + row0 + 4]);
        float4 wv = *reinterpret_cast<const float4*>(&w1s[k * K_DIM + col0]);
        float2 pr[4] = { make_float2(a0.x, a0.y), make_float2(a0.z, a0.w),
                         make_float2(a1.x, a1.y), make_float2(a1.z, a1.w) };
        float wa[4] = { wv.x, wv.y, wv.z, wv.w };
        #pragma unroll
        for (int c = 0; c < 4; c++) {
            float2 wb = make_float2(wa[c], wa[c]);
            #pragma unroll
            for (int p = 0; p < 4; p++) acc[p][c] = ffma2(pr[p], wb, acc[p][c]);
        }
    }
    // relu -> hT
    #pragma unroll
    for (int c = 0; c < 4; c++) {
        #pragma unroll
        for (int p = 0; p < 4; p++) {
            float2 v = acc[p][c];
            v.x = fmaxf(v.x, 0.f); v.y = fmaxf(v.y, 0.f);
            *reinterpret_cast<float2*>(&hT[(col0 + c) * XT_STR + row0 + 2 * p]) = v;
        }
    }
    __syncthreads();

    // Layer 2: 64 -> 2. One output element per thread (128 rows x 2 cols = 256).
    int r = tid >> 1;
    int c = tid & 1;
    if (base + r < nAgents) {
        float s = b2b[c];
        #pragma unroll 8
        for (int k = 0; k < K_DIM; k++) {
            s = fmaf(hT[k * XT_STR + r], w2b[k * 2 + c], s);
        }
        out[(base + r) * 2 + c] = s;
    }
}

// ---------------------------------------------------------------------------
extern "C" void kernel_launch(void* const* d_in, const int* in_sizes, int n_in,
                              void* d_out, int out_size)
{
    const float* neighbors = (const float*)d_in[0];
    const float* phi_w1    = (const float*)d_in[1];
    const float* phi_b1    = (const float*)d_in[2];
    const float* phi_w2    = (const float*)d_in[3];
    const float* phi_b2    = (const float*)d_in[4];
    const float* rho_w1    = (const float*)d_in[5];
    const float* rho_b1    = (const float*)d_in[6];
    const float* rho_w2    = (const float*)d_in[7];
    const float* rho_b2    = (const float*)d_in[8];
    const int*   seg       = (const int*)d_in[9];
    float* out = (float*)d_out;

    const int nN = in_sizes[9];        // N_NEIGHBORS (count of segment_ids)
    const int nA = out_size / 2;       // N_AGENTS

    const int PHI_SMEM = (4096 + 4096 + 64 * XT_STR + 64 * XT_STR + 64 + 64) * 4 + TILE * 4; // 101376
    const int RHO_SMEM = (4096 + 64 * XT_STR + 64 * XT_STR + 64 + 128 + 2) * 4;              // 84744

    cudaFuncSetAttribute(phi_kernel, cudaFuncAttributeMaxDynamicSharedMemorySize, PHI_SMEM);
    cudaFuncSetAttribute(rho_kernel, cudaFuncAttributeMaxDynamicSharedMemorySize, RHO_SMEM);

    // 1) zero the segment-sum scratch (full static buffer)
    const int n4 = MAX_AGENTS * K_DIM / 4;
    zero_kernel<<<(n4 + 255) / 256, 256>>>(n4);

    // 2) phi MLP + segment sum
    const int phi_blocks = (nN + TILE - 1) / TILE;
    phi_kernel<<<phi_blocks, 256, PHI_SMEM>>>(neighbors, phi_w1, phi_b1, phi_w2, phi_b2, seg, nN);

    // 3) rho MLP
    const int rho_blocks = (nA + TILE - 1) / TILE;
    rho_kernel<<<rho_blocks, 256, RHO_SMEM>>>(rho_w1, rho_b1, rho_w2, rho_b2, out, nA);
}